// round 2
// baseline (speedup 1.0000x reference)
#include <cuda_runtime.h>
#include <cstdint>
#include <cstddef>

#define N_TOK 4096
#define C_DIM 256
#define D_QK  32
#define BATCH 4

// Scratch for projected Q/K/V (device globals: allocation-free rule)
__device__ float g_Q[BATCH * N_TOK * D_QK];    // [b][n][32]   2 MB
__device__ float g_K[BATCH * N_TOK * D_QK];    // [b][n][32]   2 MB
__device__ float g_V[BATCH * N_TOK * C_DIM];   // [b][n][256] 16 MB

// ---------------- helpers: packed f32x2 (Blackwell FFMA2 path) ----------------
__device__ __forceinline__ unsigned long long pack2(float p) {
    unsigned long long r;
    asm("mov.b64 %0, {%1, %1};" : "=l"(r) : "f"(p));
    return r;
}
__device__ __forceinline__ void ffma2(unsigned long long& d, unsigned long long a,
                                      unsigned long long b) {
    asm("fma.rn.f32x2 %0, %1, %2, %0;" : "+l"(d) : "l"(a), "l"(b));
}
__device__ __forceinline__ void fmul2(unsigned long long& d, unsigned long long s) {
    asm("mul.rn.f32x2 %0, %0, %1;" : "+l"(d) : "l"(s));
}
__device__ __forceinline__ float2 unpack2(unsigned long long u) {
    float2 v;
    asm("mov.b64 {%0, %1}, %2;" : "=f"(v.x), "=f"(v.y) : "l"(u));
    return v;
}
__device__ __forceinline__ float fast_exp2(float x) {
    float r;
    asm("ex2.approx.ftz.f32 %0, %1;" : "=f"(r) : "f"(x));
    return r;
}

#define LOG2E 1.4426950408889634f

// ---------------- projection: Y[b][n][o] = sum_c W[o][c] * x[b][c][n] + bias[o] ----
// grid: (N_TOK/64, O/32, BATCH), block 256
__global__ __launch_bounds__(256)
void proj_kernel(const float* __restrict__ x, const float* __restrict__ W,
                 const float* __restrict__ bias, int which, int O) {
    __shared__ float xs[64 * 64];     // [c][n]
    __shared__ float ws[32 * 65];     // [o][c], padded rows (bank-conflict-free)

    const int b  = blockIdx.z;
    const int n0 = blockIdx.x * 64;
    const int o0 = blockIdx.y * 32;
    const int tid = threadIdx.x;
    const int ot = tid & 7;          // 8 o-groups  x 4 outputs
    const int nt = tid >> 3;         // 32 n-groups x 2 pixels

    float acc[4][2];
#pragma unroll
    for (int i = 0; i < 4; i++) { acc[i][0] = 0.f; acc[i][1] = 0.f; }

    const float* xb = x + (size_t)b * C_DIM * N_TOK + n0;

    for (int c0 = 0; c0 < C_DIM; c0 += 64) {
        __syncthreads();
        // load x tile [64c][64n] : 1024 float4
#pragma unroll
        for (int i = 0; i < 4; i++) {
            int f = i * 256 + tid;
            int c = f >> 4, nn = (f & 15) * 4;
            *(float4*)&xs[c * 64 + nn] =
                *(const float4*)&xb[(size_t)(c0 + c) * N_TOK + nn];
        }
        // load W tile [32o][64c] : 512 float4 -> padded smem
#pragma unroll
        for (int i = 0; i < 2; i++) {
            int f = i * 256 + tid;
            int o = f >> 4, cc = (f & 15) * 4;
            float4 t = *(const float4*)&W[(size_t)(o0 + o) * C_DIM + c0 + cc];
            float* p = &ws[o * 65 + cc];
            p[0] = t.x; p[1] = t.y; p[2] = t.z; p[3] = t.w;
        }
        __syncthreads();

#pragma unroll 16
        for (int c = 0; c < 64; c++) {
            float x0 = xs[c * 64 + nt * 2 + 0];
            float x1 = xs[c * 64 + nt * 2 + 1];
#pragma unroll
            for (int i = 0; i < 4; i++) {
                float wv = ws[(ot * 4 + i) * 65 + c];
                acc[i][0] = fmaf(wv, x0, acc[i][0]);
                acc[i][1] = fmaf(wv, x1, acc[i][1]);
            }
        }
    }

    float* Y = (which == 0) ? g_Q : (which == 1) ? g_K : g_V;
    float bs[4];
#pragma unroll
    for (int i = 0; i < 4; i++) bs[i] = bias[o0 + ot * 4 + i];

#pragma unroll
    for (int j = 0; j < 2; j++) {
        size_t n = (size_t)n0 + nt * 2 + j;
        float4 r = make_float4(acc[0][j] + bs[0], acc[1][j] + bs[1],
                               acc[2][j] + bs[2], acc[3][j] + bs[3]);
        *(float4*)&Y[((size_t)b * N_TOK + n) * O + o0 + ot * 4] = r;
    }
}

// ---------------- flash attention ----------------
// grid: (N_TOK/64, BATCH), block 256 (8 warps), 2 CTAs/SM
// warp w owns query rows m0 + w*8 .. +7 ; lane l owns output cols l*8 .. +7
// and score keys {l, l+32} within each 64-key tile.
#define SMEM_FLOATS (2048 + 64 * 33 + 4096 + 64 * 256)   // Qs, Ks(pad), Ps, Vs
#define SMEM_BYTES  (SMEM_FLOATS * 4)

__global__ __launch_bounds__(256, 2)
void attn_kernel(float* __restrict__ out) {
    extern __shared__ float sm[];
    float* Qs = sm;                        // [64][32]
    float* Ks = Qs + 2048;                 // [64][33] padded
    float* Ps = Ks + 64 * 33;              // [64][64]
    float* Vs = Ps + 4096;                 // [64][256]

    const int b   = blockIdx.y;
    const int m0  = blockIdx.x * 64;
    const int tid = threadIdx.x;
    const int w   = tid >> 5;
    const int l   = tid & 31;

    const float* Qg = g_Q + ((size_t)b * N_TOK + m0) * D_QK;
    const float* Kg = g_K + (size_t)b * N_TOK * D_QK;
    const float* Vg = g_V + (size_t)b * N_TOK * C_DIM;

    // load Q tile (512 float4)
#pragma unroll
    for (int i = 0; i < 2; i++) {
        int f = i * 256 + tid;
        *(float4*)&Qs[f * 4] = *(const float4*)&Qg[f * 4];
    }

    unsigned long long acc[8][4];          // [m][col-pair], packed f32x2
    float ml[8], li[8];
#pragma unroll
    for (int m = 0; m < 8; m++) {
        ml[m] = -3.0e38f; li[m] = 0.f;
#pragma unroll
        for (int q = 0; q < 4; q++) acc[m][q] = 0ull;
    }

    for (int kt = 0; kt < N_TOK / 64; kt++) {
        __syncthreads();   // prior tile fully consumed before overwrite
        // load K tile -> padded smem
        const float* Kt = Kg + (size_t)kt * 64 * D_QK;
#pragma unroll
        for (int i = 0; i < 2; i++) {
            int f = i * 256 + tid;
            int k = f >> 3, d4 = (f & 7) * 4;
            float4 t = *(const float4*)&Kt[k * D_QK + d4];
            float* p = &Ks[k * 33 + d4];
            p[0] = t.x; p[1] = t.y; p[2] = t.z; p[3] = t.w;
        }
        // load V tile (4096 float4)
        const float* Vt = Vg + (size_t)kt * 64 * C_DIM;
#pragma unroll
        for (int i = 0; i < 16; i++) {
            int f = i * 256 + tid;
            *(float4*)&Vs[f * 4] = *(const float4*)&Vt[f * 4];
        }
        __syncthreads();

        // ---- S = Q K^T  (keys l and l+32, rows w*8..+7) ----
        float s0[8], s1[8];
#pragma unroll
        for (int m = 0; m < 8; m++) { s0[m] = 0.f; s1[m] = 0.f; }
        const float* K0 = &Ks[l * 33];
        const float* K1 = &Ks[(l + 32) * 33];
        const float* Qw = &Qs[w * 8 * D_QK];
#pragma unroll
        for (int d0 = 0; d0 < D_QK; d0 += 4) {
            float k0[4], k1[4];
#pragma unroll
            for (int i = 0; i < 4; i++) { k0[i] = K0[d0 + i]; k1[i] = K1[d0 + i]; }
#pragma unroll
            for (int m = 0; m < 8; m++) {
                float4 q = *(const float4*)&Qw[m * D_QK + d0];
                s0[m] = fmaf(q.x, k0[0], s0[m]); s0[m] = fmaf(q.y, k0[1], s0[m]);
                s0[m] = fmaf(q.z, k0[2], s0[m]); s0[m] = fmaf(q.w, k0[3], s0[m]);
                s1[m] = fmaf(q.x, k1[0], s1[m]); s1[m] = fmaf(q.y, k1[1], s1[m]);
                s1[m] = fmaf(q.z, k1[2], s1[m]); s1[m] = fmaf(q.w, k1[3], s1[m]);
            }
        }

        // ---- online softmax (per warp-row) ----
        float* Pw = &Ps[w * 8 * 64];
#pragma unroll
        for (int m = 0; m < 8; m++) {
            float tm = fmaxf(s0[m], s1[m]);
#pragma unroll
            for (int off = 16; off > 0; off >>= 1)
                tm = fmaxf(tm, __shfl_xor_sync(0xffffffffu, tm, off));
            float mnew = fmaxf(ml[m], tm);
            float p0 = fast_exp2((s0[m] - mnew) * LOG2E);
            float p1 = fast_exp2((s1[m] - mnew) * LOG2E);
            float ts = p0 + p1;
#pragma unroll
            for (int off = 16; off > 0; off >>= 1)
                ts += __shfl_xor_sync(0xffffffffu, ts, off);
            float scale = fast_exp2((ml[m] - mnew) * LOG2E);
            li[m] = li[m] * scale + ts;
            ml[m] = mnew;
            if (scale < 1.f) {   // uniform across warp; rare after first tiles
                unsigned long long ss = pack2(scale);
                fmul2(acc[m][0], ss); fmul2(acc[m][1], ss);
                fmul2(acc[m][2], ss); fmul2(acc[m][3], ss);
            }
            Pw[m * 64 + l]      = p0;
            Pw[m * 64 + l + 32] = p1;
        }
        __syncwarp();

        // ---- O += P V  (packed f32x2 FMAs) ----
        const int c0 = l * 8;
#pragma unroll 2
        for (int k = 0; k < 64; k++) {
            const float* vrow = &Vs[k * C_DIM + c0];
            const ulonglong2* vp = (const ulonglong2*)vrow;
            ulonglong2 va = vp[0];     // cols c0..c0+3
            ulonglong2 vb = vp[1];     // cols c0+4..c0+7
#pragma unroll
            for (int m = 0; m < 8; m++) {
                unsigned long long pp = pack2(Pw[m * 64 + k]);
                ffma2(acc[m][0], va.x, pp);
                ffma2(acc[m][1], va.y, pp);
                ffma2(acc[m][2], vb.x, pp);
                ffma2(acc[m][3], vb.y, pp);
            }
        }
    }

    // ---- normalize + store out[b][c][n] (vectorized along n) ----
    float inv[8];
#pragma unroll
    for (int m = 0; m < 8; m++) inv[m] = 1.f / li[m];

    float* ob = out + (size_t)b * C_DIM * N_TOK + m0 + w * 8;
#pragma unroll
    for (int q = 0; q < 4; q++) {
        float2 t[8];
#pragma unroll
        for (int m = 0; m < 8; m++) {
            t[m] = unpack2(acc[m][q]);
            t[m].x *= inv[m]; t[m].y *= inv[m];
        }
        int c = l * 8 + q * 2;
        float4 r0 = make_float4(t[0].x, t[1].x, t[2].x, t[3].x);
        float4 r1 = make_float4(t[4].x, t[5].x, t[6].x, t[7].x);
        *(float4*)&ob[(size_t)c * N_TOK]     = r0;
        *(float4*)&ob[(size_t)c * N_TOK + 4] = r1;
        float4 r2 = make_float4(t[0].y, t[1].y, t[2].y, t[3].y);
        float4 r3 = make_float4(t[4].y, t[5].y, t[6].y, t[7].y);
        *(float4*)&ob[(size_t)(c + 1) * N_TOK]     = r2;
        *(float4*)&ob[(size_t)(c + 1) * N_TOK + 4] = r3;
    }
}

// ---------------- launch ----------------
extern "C" void kernel_launch(void* const* d_in, const int* in_sizes, int n_in,
                              void* d_out, int out_size) {
    (void)in_sizes; (void)n_in; (void)out_size;
    const float* x  = (const float*)d_in[0];
    const float* Wq = (const float*)d_in[1];
    const float* bq = (const float*)d_in[2];
    const float* Wk = (const float*)d_in[3];
    const float* bk = (const float*)d_in[4];
    const float* Wv = (const float*)d_in[5];
    const float* bv = (const float*)d_in[6];
    float* out = (float*)d_out;

    cudaFuncSetAttribute(attn_kernel, cudaFuncAttributeMaxDynamicSharedMemorySize,
                         SMEM_BYTES);

    dim3 gqk(N_TOK / 64, 1, BATCH);
    proj_kernel<<<gqk, 256>>>(x, Wq, bq, 0, D_QK);
    proj_kernel<<<gqk, 256>>>(x, Wk, bk, 1, D_QK);
    dim3 gv(N_TOK / 64, C_DIM / 32, BATCH);
    proj_kernel<<<gv, 256>>>(x, Wv, bv, 2, C_DIM);

    dim3 ga(N_TOK / 64, BATCH);
    attn_kernel<<<ga, 256, SMEM_BYTES>>>(out);
}

// round 4
// speedup vs baseline: 4.2133x; 4.2133x over previous
#include <cuda_runtime.h>
#include <cuda_fp16.h>
#include <cstdint>
#include <cstddef>

#define N_TOK 4096
#define C_DIM 256
#define D_QK  32
#define BATCH 4
#define BLK_M 128
#define BLK_N 64
#define NKT   (N_TOK / BLK_N)
#define LOG2E 1.4426950408889634f

// fp16 operand buffers written by projection kernels
__device__ __half g_Qh[BATCH * N_TOK * D_QK];   // pre-scaled by LOG2E, hi
__device__ __half g_Ql[BATCH * N_TOK * D_QK];   // lo residual
__device__ __half g_Kh[BATCH * N_TOK * D_QK];
__device__ __half g_Kl[BATCH * N_TOK * D_QK];
__device__ __half g_Vh[BATCH * N_TOK * C_DIM];  // single fp16

// ------------------------------------------------------------- PTX helpers
__device__ __forceinline__ uint32_t smem_u32(const void* p) {
    uint32_t a;
    asm("{ .reg .u64 t; cvta.to.shared.u64 t, %1; cvt.u32.u64 %0, t; }"
        : "=r"(a) : "l"(p));
    return a;
}
__device__ __forceinline__ float fast_exp2(float x) {
    float r; asm("ex2.approx.ftz.f32 %0, %1;" : "=f"(r) : "f"(x)); return r;
}
__device__ __forceinline__ uint32_t packh2(float lo, float hi) {
    uint32_t d;
    asm("cvt.rn.f16x2.f32 %0, %1, %2;" : "=r"(d) : "f"(hi), "f"(lo));
    return d;
}
#define CPASYNC(dst, src) \
    asm volatile("cp.async.cg.shared.global [%0], [%1], 16;" \
                 :: "r"(dst), "l"(src))
#define CP_COMMIT() asm volatile("cp.async.commit_group;" ::: "memory")
#define CP_WAIT(n)  asm volatile("cp.async.wait_group %0;" :: "n"(n) : "memory")

__device__ __forceinline__ void ldsm_x2(uint32_t& d0, uint32_t& d1, uint32_t a) {
    asm volatile("ldmatrix.sync.aligned.m8n8.x2.shared.b16 {%0,%1}, [%2];"
                 : "=r"(d0), "=r"(d1) : "r"(a));
}
__device__ __forceinline__ void ldsm_x4(uint32_t* d, uint32_t a) {
    asm volatile("ldmatrix.sync.aligned.m8n8.x4.shared.b16 {%0,%1,%2,%3}, [%4];"
                 : "=r"(d[0]), "=r"(d[1]), "=r"(d[2]), "=r"(d[3]) : "r"(a));
}
__device__ __forceinline__ void ldsm_x4t(uint32_t* d, uint32_t a) {
    asm volatile("ldmatrix.sync.aligned.m8n8.x4.trans.shared.b16 {%0,%1,%2,%3}, [%4];"
                 : "=r"(d[0]), "=r"(d[1]), "=r"(d[2]), "=r"(d[3]) : "r"(a));
}
__device__ __forceinline__ void mma16816(float* c, const uint32_t* a,
                                         uint32_t b0, uint32_t b1) {
    asm volatile(
        "mma.sync.aligned.m16n8k16.row.col.f32.f16.f16.f32 "
        "{%0,%1,%2,%3}, {%4,%5,%6,%7}, {%8,%9}, {%0,%1,%2,%3};"
        : "+f"(c[0]), "+f"(c[1]), "+f"(c[2]), "+f"(c[3])
        : "r"(a[0]), "r"(a[1]), "r"(a[2]), "r"(a[3]), "r"(b0), "r"(b1));
}

// ------------------------------------------------------------- smem layout
#define PAD_K   80                         // 64B K row + 16B pad (bank spread)
#define PAD_V   528                        // 512B V row + 16B pad
#define KBYTES  (BLK_N * PAD_K)            // 5120
#define VOFF    (2 * KBYTES)               // 10240
#define VBYTES  (BLK_N * PAD_V)            // 33792
#define BUF_BYTES (VOFF + VBYTES)          // 44032
#define SM_TOTAL  (2 * BUF_BYTES)          // 88064

// ---------------- projection: fp32 compute, fp16(+split) output ------------
__global__ __launch_bounds__(256)
void proj_kernel(const float* __restrict__ x, const float* __restrict__ W,
                 const float* __restrict__ bias, int which) {
    __shared__ float xs[64 * 64];
    __shared__ float ws[32 * 65];

    const int b  = blockIdx.z;
    const int n0 = blockIdx.x * 64;
    const int o0 = blockIdx.y * 32;
    const int tid = threadIdx.x;
    const int ot = tid & 7;
    const int nt = tid >> 3;

    float acc[4][2];
#pragma unroll
    for (int i = 0; i < 4; i++) { acc[i][0] = 0.f; acc[i][1] = 0.f; }

    const float* xb = x + (size_t)b * C_DIM * N_TOK + n0;

    for (int c0 = 0; c0 < C_DIM; c0 += 64) {
        __syncthreads();
#pragma unroll
        for (int i = 0; i < 4; i++) {
            int f = i * 256 + tid;
            int c = f >> 4, nn = (f & 15) * 4;
            *(float4*)&xs[c * 64 + nn] =
                *(const float4*)&xb[(size_t)(c0 + c) * N_TOK + nn];
        }
#pragma unroll
        for (int i = 0; i < 2; i++) {
            int f = i * 256 + tid;
            int o = f >> 4, cc = (f & 15) * 4;
            float4 t = *(const float4*)&W[(size_t)(o0 + o) * C_DIM + c0 + cc];
            float* p = &ws[o * 65 + cc];
            p[0] = t.x; p[1] = t.y; p[2] = t.z; p[3] = t.w;
        }
        __syncthreads();

#pragma unroll 16
        for (int c = 0; c < 64; c++) {
            float x0 = xs[c * 64 + nt * 2 + 0];
            float x1 = xs[c * 64 + nt * 2 + 1];
#pragma unroll
            for (int i = 0; i < 4; i++) {
                float wv = ws[(ot * 4 + i) * 65 + c];
                acc[i][0] = fmaf(wv, x0, acc[i][0]);
                acc[i][1] = fmaf(wv, x1, acc[i][1]);
            }
        }
    }

    float bs[4];
#pragma unroll
    for (int i = 0; i < 4; i++) bs[i] = bias[o0 + ot * 4 + i];

#pragma unroll
    for (int j = 0; j < 2; j++) {
        size_t n = (size_t)n0 + nt * 2 + j;
        float v[4];
#pragma unroll
        for (int i = 0; i < 4; i++) v[i] = acc[i][j] + bs[i];

        if (which == 2) {            // V: single fp16, [b][n][256]
            size_t base = ((size_t)b * N_TOK + n) * C_DIM + o0 + ot * 4;
            __half2* d = (__half2*)&g_Vh[base];
            d[0] = __halves2half2(__float2half_rn(v[0]), __float2half_rn(v[1]));
            d[1] = __halves2half2(__float2half_rn(v[2]), __float2half_rn(v[3]));
        } else {                     // Q/K: hi/lo split, [b][n][32]
            if (which == 0) {
#pragma unroll
                for (int i = 0; i < 4; i++) v[i] *= LOG2E;
            }
            __half hi[4], lo[4];
#pragma unroll
            for (int i = 0; i < 4; i++) {
                hi[i] = __float2half_rn(v[i]);
                lo[i] = __float2half_rn(v[i] - __half2float(hi[i]));
            }
            size_t base = ((size_t)b * N_TOK + n) * D_QK + o0 + ot * 4;
            __half2* dh = (which == 0) ? (__half2*)&g_Qh[base] : (__half2*)&g_Kh[base];
            __half2* dl = (which == 0) ? (__half2*)&g_Ql[base] : (__half2*)&g_Kl[base];
            dh[0] = __halves2half2(hi[0], hi[1]);
            dh[1] = __halves2half2(hi[2], hi[3]);
            dl[0] = __halves2half2(lo[0], lo[1]);
            dl[1] = __halves2half2(lo[2], lo[3]);
        }
    }
}

// ---------------------- HMMA flash attention --------------------------------
__global__ __launch_bounds__(256, 1)
void attn_hmma(float* __restrict__ out) {
    extern __shared__ char smc[];
    const uint32_t sb = smem_u32(smc);
    const int tid = threadIdx.x;
    const int w = tid >> 5, lane = tid & 31;
    const int g = lane >> 2, c4 = lane & 3;
    const int b = blockIdx.y, m0 = blockIdx.x * BLK_M;

    // ---- stage Q tile (hi/lo) into buf0 region, build A-frags -------------
    {
        const __half* Qh = g_Qh + ((size_t)b * N_TOK + m0) * D_QK;
        const __half* Ql = g_Ql + ((size_t)b * N_TOK + m0) * D_QK;
#pragma unroll
        for (int i = 0; i < 2; i++) {
            int idx = i * 256 + tid;              // 512 chunks of 16B
            int row = idx >> 2, cc = idx & 3;
            uint32_t dst = sb + row * PAD_K + cc * 16;
            CPASYNC(dst, Qh + row * D_QK + cc * 8);
            CPASYNC(dst + (uint32_t)(BLK_M * PAD_K), Ql + row * D_QK + cc * 8);
        }
        CP_COMMIT();
        CP_WAIT(0);
        __syncthreads();
    }
    uint32_t qh[2][4], ql[2][4];
    {
        uint32_t qoff = (uint32_t)((16 * w + ((lane >> 3) & 1) * 8 + (lane & 7)) * PAD_K
                                   + (lane >> 4) * 16);
#pragma unroll
        for (int kk = 0; kk < 2; kk++) {
            ldsm_x4(qh[kk], sb + qoff + kk * 32);
            ldsm_x4(ql[kk], sb + qoff + kk * 32 + (uint32_t)(BLK_M * PAD_K));
        }
    }
    __syncthreads();

    // ---- per-thread cp.async source/dest indices --------------------------
    const __half* Kh = g_Kh + (size_t)b * N_TOK * D_QK;
    const __half* Kl = g_Kl + (size_t)b * N_TOK * D_QK;
    const __half* Vh = g_Vh + (size_t)b * N_TOK * C_DIM;
    const int krow = tid >> 2, kcc = tid & 3;     // 256 chunks for each K array

    // ldmatrix per-thread bases
    const int ls = lane & 15;
    const int lr = ls & 7, lsel = ls >> 3;
    const uint32_t kb = (uint32_t)(lr * PAD_K + lsel * 16);
    const uint32_t vb = (uint32_t)(VOFF + (lsel * 8 + lr) * PAD_V + (lane >> 4) * 16);

    // ---- prologue: issue tiles 0 and 1 ------------------------------------
#pragma unroll
    for (int t = 0; t < 2; t++) {
        uint32_t bs_ = sb + t * BUF_BYTES;
        const int kt0 = t * BLK_N;
        {
            uint32_t dst = bs_ + krow * PAD_K + kcc * 16;
            CPASYNC(dst, Kh + (kt0 + krow) * D_QK + kcc * 8);
            CPASYNC(dst + (uint32_t)KBYTES, Kl + (kt0 + krow) * D_QK + kcc * 8);
        }
#pragma unroll
        for (int i = 0; i < 8; i++) {
            int idx = i * 256 + tid;               // 2048 chunks of 16B
            int row = idx >> 5, cc = idx & 31;
            CPASYNC(bs_ + VOFF + row * PAD_V + cc * 16,
                    Vh + (size_t)(kt0 + row) * C_DIM + cc * 8);
        }
        CP_COMMIT();
    }

    // ---- state ------------------------------------------------------------
    float o[32][4];
#pragma unroll
    for (int n = 0; n < 32; n++)
#pragma unroll
        for (int j = 0; j < 4; j++) o[n][j] = 0.f;
    float m2l = -1e30f, m2h = -1e30f, ll = 0.f, lh = 0.f;

    // ---- main loop ---------------------------------------------------------
    for (int kt = 0; kt < NKT; kt++) {
        CP_WAIT(1);
        __syncthreads();
        const uint32_t bs_ = sb + (kt & 1) * BUF_BYTES;

        // ----- S = Q K^T : 3-term hi/lo fp16 -----
        float sf[8][4];
#pragma unroll
        for (int n = 0; n < 8; n++)
#pragma unroll
            for (int j = 0; j < 4; j++) sf[n][j] = 0.f;

#pragma unroll
        for (int n = 0; n < 8; n++) {
#pragma unroll
            for (int kk = 0; kk < 2; kk++) {
                uint32_t a0, a1, b0, b1;
                uint32_t addr = bs_ + kb + n * (8 * PAD_K) + kk * 32;
                ldsm_x2(a0, a1, addr);                        // Kh
                ldsm_x2(b0, b1, addr + (uint32_t)KBYTES);     // Kl
                mma16816(sf[n], qh[kk], a0, a1);
                mma16816(sf[n], qh[kk], b0, b1);
                mma16816(sf[n], ql[kk], a0, a1);
            }
        }

        // ----- online softmax (base-2; Q pre-scaled by log2e) -----
        float rml = -1e30f, rmh = -1e30f;
#pragma unroll
        for (int n = 0; n < 8; n++) {
            rml = fmaxf(rml, fmaxf(sf[n][0], sf[n][1]));
            rmh = fmaxf(rmh, fmaxf(sf[n][2], sf[n][3]));
        }
#pragma unroll
        for (int off = 1; off <= 2; off <<= 1) {
            rml = fmaxf(rml, __shfl_xor_sync(0xffffffffu, rml, off));
            rmh = fmaxf(rmh, __shfl_xor_sync(0xffffffffu, rmh, off));
        }
        float mnl = fmaxf(m2l, rml), mnh = fmaxf(m2h, rmh);
        bool ch = (mnl != m2l) || (mnh != m2h);
        if (__any_sync(0xffffffffu, ch)) {
            float sl = fast_exp2(m2l - mnl), sh = fast_exp2(m2h - mnh);
            ll *= sl; lh *= sh;
#pragma unroll
            for (int n = 0; n < 32; n++) {
                o[n][0] *= sl; o[n][1] *= sl;
                o[n][2] *= sh; o[n][3] *= sh;
            }
        }
        m2l = mnl; m2h = mnh;

#pragma unroll
        for (int n = 0; n < 8; n++) {
            sf[n][0] = fast_exp2(sf[n][0] - mnl);
            sf[n][1] = fast_exp2(sf[n][1] - mnl);
            sf[n][2] = fast_exp2(sf[n][2] - mnh);
            sf[n][3] = fast_exp2(sf[n][3] - mnh);
            ll += sf[n][0] + sf[n][1];
            lh += sf[n][2] + sf[n][3];
        }

        // ----- O += P V : single fp16 -----
#pragma unroll
        for (int kk = 0; kk < 4; kk++) {
            uint32_t pa[4];
            pa[0] = packh2(sf[2 * kk][0],     sf[2 * kk][1]);
            pa[1] = packh2(sf[2 * kk][2],     sf[2 * kk][3]);
            pa[2] = packh2(sf[2 * kk + 1][0], sf[2 * kk + 1][1]);
            pa[3] = packh2(sf[2 * kk + 1][2], sf[2 * kk + 1][3]);
            uint32_t va = bs_ + vb + kk * (16 * PAD_V);
#pragma unroll
            for (int n = 0; n < 32; n += 2) {
                uint32_t bf[4];
                ldsm_x4t(bf, va + n * 16);
                mma16816(o[n],     pa, bf[0], bf[1]);
                mma16816(o[n + 1], pa, bf[2], bf[3]);
            }
        }

        __syncthreads();

        // ----- issue tile kt+2 -----
        if (kt + 2 < NKT) {
            uint32_t nb = sb + (kt & 1) * BUF_BYTES;
            const int kt0 = (kt + 2) * BLK_N;
            uint32_t dst = nb + krow * PAD_K + kcc * 16;
            CPASYNC(dst, Kh + (kt0 + krow) * D_QK + kcc * 8);
            CPASYNC(dst + (uint32_t)KBYTES, Kl + (kt0 + krow) * D_QK + kcc * 8);
#pragma unroll
            for (int i = 0; i < 8; i++) {
                int idx = i * 256 + tid;
                int row = idx >> 5, cc = idx & 31;
                CPASYNC(nb + VOFF + row * PAD_V + cc * 16,
                        Vh + (size_t)(kt0 + row) * C_DIM + cc * 8);
            }
        }
        CP_COMMIT();
    }

    // ---- epilogue ----------------------------------------------------------
#pragma unroll
    for (int off = 1; off <= 2; off <<= 1) {
        ll += __shfl_xor_sync(0xffffffffu, ll, off);
        lh += __shfl_xor_sync(0xffffffffu, lh, off);
    }
    const float il = 1.f / ll, ih = 1.f / lh;
    const int tok_lo = m0 + 16 * w + g, tok_hi = tok_lo + 8;
    float* ob = out + (size_t)b * C_DIM * N_TOK;
#pragma unroll
    for (int n = 0; n < 32; n++) {
        int ch0 = 8 * n + 2 * c4;
        ob[(size_t)ch0 * N_TOK + tok_lo]       = o[n][0] * il;
        ob[(size_t)(ch0 + 1) * N_TOK + tok_lo] = o[n][1] * il;
        ob[(size_t)ch0 * N_TOK + tok_hi]       = o[n][2] * ih;
        ob[(size_t)(ch0 + 1) * N_TOK + tok_hi] = o[n][3] * ih;
    }
}

// ---------------- launch ----------------
extern "C" void kernel_launch(void* const* d_in, const int* in_sizes, int n_in,
                              void* d_out, int out_size) {
    (void)in_sizes; (void)n_in; (void)out_size;
    const float* x  = (const float*)d_in[0];
    const float* Wq = (const float*)d_in[1];
    const float* bq = (const float*)d_in[2];
    const float* Wk = (const float*)d_in[3];
    const float* bk = (const float*)d_in[4];
    const float* Wv = (const float*)d_in[5];
    const float* bv = (const float*)d_in[6];
    float* out = (float*)d_out;

    cudaFuncSetAttribute(attn_hmma, cudaFuncAttributeMaxDynamicSharedMemorySize,
                         SM_TOTAL);

    dim3 gqk(N_TOK / 64, 1, BATCH);
    proj_kernel<<<gqk, 256>>>(x, Wq, bq, 0);
    proj_kernel<<<gqk, 256>>>(x, Wk, bk, 1);
    dim3 gv(N_TOK / 64, C_DIM / 32, BATCH);
    proj_kernel<<<gv, 256>>>(x, Wv, bv, 2);

    dim3 ga(N_TOK / BLK_M, BATCH);
    attn_hmma<<<ga, 256, SM_TOTAL>>>(out);
}